// round 7
// baseline (speedup 1.0000x reference)
#include <cuda_runtime.h>
#include <cuda_bf16.h>

// LIF neuron update (SpikeLayer.update_neurons), one timestep.
// Elementwise over N = 12,845,056 fp32 elements. 5 inputs, 6 stacked outputs.
// HBM-bound; traffic irreducible at 11*N*4B = 565 MB.
// R1 shape (1 float4 group/thread, 32 regs, high occ) + .cs stores only.

#define V_THRESH   1.0f
#define TIME_C     0.5f
#define REFRAC_NEW 2.5f   // TIME + TAU_REFRAC

__device__ __forceinline__ void stcs4(float4* p, float4 v) {
    asm volatile("st.global.cs.v4.f32 [%0], {%1,%2,%3,%4};"
                 :: "l"(p), "f"(v.x), "f"(v.y), "f"(v.z), "f"(v.w) : "memory");
}

__global__ void __launch_bounds__(512) lif_update_kernel(
    const float4* __restrict__ impulse,
    const float4* __restrict__ mem,
    const float4* __restrict__ mem_acc,
    const float4* __restrict__ refrac_until,
    const float4* __restrict__ spikecounts,
    float4* __restrict__ out,     // 6 planes of n4 float4 each
    int n4)
{
    int i = blockIdx.x * blockDim.x + threadIdx.x;
    if (i >= n4) return;

    // Front-batch all 5 loads (default caching — won vs .cs in R2).
    float4 imp = impulse[i];
    float4 m   = mem[i];
    float4 ma  = mem_acc[i];
    float4 ru  = refrac_until[i];
    float4 sc  = spikecounts[i];

    float4 o_spk, o_mem, o_macc, o_ru, o_cnt, o_st;

    #pragma unroll
    for (int c = 0; c < 4; c++) {
        float impv = (&imp.x)[c];
        float mv   = (&m.x)[c];
        float mav  = (&ma.x)[c];
        float ruv  = (&ru.x)[c];
        float scv  = (&sc.x)[c];

        float masked   = (ruv > TIME_C) ? 0.0f : impv;
        float new_mem  = mv + masked;
        float new_macc = mav + masked;
        bool  fire     = (new_mem >= V_THRESH);

        (&o_spk.x)[c]  = fire ? V_THRESH : 0.0f;
        (&o_mem.x)[c]  = fire ? (new_mem - V_THRESH) : new_mem;
        (&o_macc.x)[c] = new_macc;
        (&o_ru.x)[c]   = fire ? REFRAC_NEW : ruv;
        (&o_cnt.x)[c]  = scv + (fire ? 1.0f : 0.0f);
        (&o_st.x)[c]   = fire ? (V_THRESH * TIME_C) : 0.0f;
    }

    size_t N = (size_t)n4;
    stcs4(out + 0 * N + i, o_spk);
    stcs4(out + 1 * N + i, o_mem);
    stcs4(out + 2 * N + i, o_macc);
    stcs4(out + 3 * N + i, o_ru);
    stcs4(out + 4 * N + i, o_cnt);
    stcs4(out + 5 * N + i, o_st);
}

extern "C" void kernel_launch(void* const* d_in, const int* in_sizes, int n_in,
                              void* d_out, int out_size)
{
    const float* impulse      = (const float*)d_in[0];
    const float* mem          = (const float*)d_in[1];
    const float* mem_acc      = (const float*)d_in[2];
    const float* refrac_until = (const float*)d_in[3];
    const float* spikecounts  = (const float*)d_in[4];

    int n  = in_sizes[0];       // 12,845,056
    int n4 = n / 4;             // 3,211,264

    int threads = 512;
    int blocks  = (n4 + threads - 1) / threads;   // 6272

    lif_update_kernel<<<blocks, threads>>>(
        (const float4*)impulse,
        (const float4*)mem,
        (const float4*)mem_acc,
        (const float4*)refrac_until,
        (const float4*)spikecounts,
        (float4*)d_out,
        n4);
}

// round 9
// speedup vs baseline: 1.0114x; 1.0114x over previous
#include <cuda_runtime.h>
#include <cuda_bf16.h>

// LIF neuron update (SpikeLayer.update_neurons), one timestep.
// Elementwise over N = 12,845,056 fp32 elements. 5 inputs, 6 stacked outputs.
// HBM-bound: traffic irreducible at 11*N*4B = 565 MB; measured ceiling
// ~6.35 TB/s for this 5-read/6-write stream mix. Empirically optimal config
// (R1): plain float4, 256 threads, 1 group/thread, 32 regs, 75% occ.
// Tested and rejected: .cs hints (load and/or store), ILP=2, 512-thread blocks
// — all regressed 1-1.5%.

#define V_THRESH   1.0f
#define TIME_C     0.5f
#define REFRAC_NEW 2.5f   // TIME + TAU_REFRAC

__global__ void __launch_bounds__(256) lif_update_kernel(
    const float4* __restrict__ impulse,
    const float4* __restrict__ mem,
    const float4* __restrict__ mem_acc,
    const float4* __restrict__ refrac_until,
    const float4* __restrict__ spikecounts,
    float4* __restrict__ out,     // 6 planes of n4 float4 each
    int n4)
{
    int i = blockIdx.x * blockDim.x + threadIdx.x;
    if (i >= n4) return;

    // Front-batch all 5 loads.
    float4 imp = impulse[i];
    float4 m   = mem[i];
    float4 ma  = mem_acc[i];
    float4 ru  = refrac_until[i];
    float4 sc  = spikecounts[i];

    float4 o_spk, o_mem, o_macc, o_ru, o_cnt, o_st;

    #pragma unroll
    for (int c = 0; c < 4; c++) {
        float impv = (&imp.x)[c];
        float mv   = (&m.x)[c];
        float mav  = (&ma.x)[c];
        float ruv  = (&ru.x)[c];
        float scv  = (&sc.x)[c];

        float masked   = (ruv > TIME_C) ? 0.0f : impv;
        float new_mem  = mv + masked;
        float new_macc = mav + masked;
        bool  fire     = (new_mem >= V_THRESH);

        (&o_spk.x)[c]  = fire ? V_THRESH : 0.0f;
        (&o_mem.x)[c]  = fire ? (new_mem - V_THRESH) : new_mem;
        (&o_macc.x)[c] = new_macc;
        (&o_ru.x)[c]   = fire ? REFRAC_NEW : ruv;
        (&o_cnt.x)[c]  = scv + (fire ? 1.0f : 0.0f);
        (&o_st.x)[c]   = fire ? (V_THRESH * TIME_C) : 0.0f;
    }

    size_t N = (size_t)n4;
    out[0 * N + i] = o_spk;
    out[1 * N + i] = o_mem;
    out[2 * N + i] = o_macc;
    out[3 * N + i] = o_ru;
    out[4 * N + i] = o_cnt;
    out[5 * N + i] = o_st;
}

extern "C" void kernel_launch(void* const* d_in, const int* in_sizes, int n_in,
                              void* d_out, int out_size)
{
    const float* impulse      = (const float*)d_in[0];
    const float* mem          = (const float*)d_in[1];
    const float* mem_acc      = (const float*)d_in[2];
    const float* refrac_until = (const float*)d_in[3];
    const float* spikecounts  = (const float*)d_in[4];

    int n  = in_sizes[0];       // 12,845,056
    int n4 = n / 4;             // 3,211,264

    int threads = 256;
    int blocks  = (n4 + threads - 1) / threads;   // 12,544

    lif_update_kernel<<<blocks, threads>>>(
        (const float4*)impulse,
        (const float4*)mem,
        (const float4*)mem_acc,
        (const float4*)refrac_until,
        (const float4*)spikecounts,
        (float4*)d_out,
        n4);
}

// round 12
// speedup vs baseline: 1.0215x; 1.0100x over previous
#include <cuda_runtime.h>
#include <cuda_bf16.h>
#include <cstdint>

// LIF neuron update (SpikeLayer.update_neurons), one timestep.
// Elementwise over N = 12,845,056 fp32 elements. 5 inputs, 6 stacked outputs.
// HBM-bound: 565 MB irreducible traffic, measured ceiling ~6.35 TB/s.
// R9 experiment: 256-bit (v8.b32) loads/stores — sm_100+ LDG.E.256/STG.E.256.
// Each thread handles 8 consecutive floats; warp touches 1024B per access.

#define V_THRESH   1.0f
#define TIME_C     0.5f
#define REFRAC_NEW 2.5f   // TIME + TAU_REFRAC

__device__ __forceinline__ void ldg_v8(const float* p, float* v) {
    uint32_t r0, r1, r2, r3, r4, r5, r6, r7;
    asm volatile("ld.global.v8.b32 {%0,%1,%2,%3,%4,%5,%6,%7}, [%8];"
                 : "=r"(r0), "=r"(r1), "=r"(r2), "=r"(r3),
                   "=r"(r4), "=r"(r5), "=r"(r6), "=r"(r7)
                 : "l"(p));
    v[0] = __uint_as_float(r0); v[1] = __uint_as_float(r1);
    v[2] = __uint_as_float(r2); v[3] = __uint_as_float(r3);
    v[4] = __uint_as_float(r4); v[5] = __uint_as_float(r5);
    v[6] = __uint_as_float(r6); v[7] = __uint_as_float(r7);
}

__device__ __forceinline__ void stg_v8(float* p, const float* v) {
    asm volatile("st.global.v8.b32 [%0], {%1,%2,%3,%4,%5,%6,%7,%8};"
                 :: "l"(p),
                    "r"(__float_as_uint(v[0])), "r"(__float_as_uint(v[1])),
                    "r"(__float_as_uint(v[2])), "r"(__float_as_uint(v[3])),
                    "r"(__float_as_uint(v[4])), "r"(__float_as_uint(v[5])),
                    "r"(__float_as_uint(v[6])), "r"(__float_as_uint(v[7]))
                 : "memory");
}

__global__ void __launch_bounds__(256) lif_update_kernel(
    const float* __restrict__ impulse,
    const float* __restrict__ mem,
    const float* __restrict__ mem_acc,
    const float* __restrict__ refrac_until,
    const float* __restrict__ spikecounts,
    float* __restrict__ out,      // 6 planes of n floats each
    int n8, size_t n)
{
    int t = blockIdx.x * blockDim.x + threadIdx.x;
    if (t >= n8) return;
    size_t base = (size_t)t * 8;

    float imp[8], m[8], ma[8], ru[8], sc[8];
    ldg_v8(impulse      + base, imp);
    ldg_v8(mem          + base, m);
    ldg_v8(mem_acc      + base, ma);
    ldg_v8(refrac_until + base, ru);
    ldg_v8(spikecounts  + base, sc);

    float o_spk[8], o_mem[8], o_macc[8], o_ru[8], o_cnt[8], o_st[8];

    #pragma unroll
    for (int c = 0; c < 8; c++) {
        float masked   = (ru[c] > TIME_C) ? 0.0f : imp[c];
        float new_mem  = m[c] + masked;
        float new_macc = ma[c] + masked;
        bool  fire     = (new_mem >= V_THRESH);

        o_spk[c]  = fire ? V_THRESH : 0.0f;
        o_mem[c]  = fire ? (new_mem - V_THRESH) : new_mem;
        o_macc[c] = new_macc;
        o_ru[c]   = fire ? REFRAC_NEW : ru[c];
        o_cnt[c]  = sc[c] + (fire ? 1.0f : 0.0f);
        o_st[c]   = fire ? (V_THRESH * TIME_C) : 0.0f;
    }

    stg_v8(out + 0 * n + base, o_spk);
    stg_v8(out + 1 * n + base, o_mem);
    stg_v8(out + 2 * n + base, o_macc);
    stg_v8(out + 3 * n + base, o_ru);
    stg_v8(out + 4 * n + base, o_cnt);
    stg_v8(out + 5 * n + base, o_st);
}

extern "C" void kernel_launch(void* const* d_in, const int* in_sizes, int n_in,
                              void* d_out, int out_size)
{
    const float* impulse      = (const float*)d_in[0];
    const float* mem          = (const float*)d_in[1];
    const float* mem_acc      = (const float*)d_in[2];
    const float* refrac_until = (const float*)d_in[3];
    const float* spikecounts  = (const float*)d_in[4];

    int n  = in_sizes[0];       // 12,845,056 (divisible by 8)
    int n8 = n / 8;             // 1,605,632

    int threads = 256;
    int blocks  = (n8 + threads - 1) / threads;   // 6272

    lif_update_kernel<<<blocks, threads>>>(
        impulse, mem, mem_acc, refrac_until, spikecounts,
        (float*)d_out, n8, (size_t)n);
}